// round 2
// baseline (speedup 1.0000x reference)
#include <cuda_runtime.h>
#include <cstdint>

#define SMS 68          // smem row stride in floats (bank-conflict-free, 16B-aligned)
#define NSTEP 256

// ---------------- persistent device state (no allocation allowed) ----------------
__device__ __align__(16) float g_FC[256*2048];        // fc_in-layout state (== dec initially)
__device__ __align__(16) float g_OUT[256*512];        // sigmoid(map) output (x for layer0)
__device__ __align__(16) float g_X1[256*512];         // raw h2 of layer0 (x for layer1)
__device__ __align__(16) float g_H[2][2][256*512];    // [parity][layer] carried tanh(h)
__device__ __align__(16) float g_C[2][2][256*512];    // [parity][layer] carried tanh(c)
__device__ __align__(16) float g_Bfc[256*2048];       // tf32-rounded fc_w, k-major
__device__ __align__(16) float g_Bmap[2048*512];      // tf32-rounded map_w, k-major
__device__ __align__(16) float g_BL[2][1024*2048];    // tf32 [wih;whh], gate-interleaved cols
__device__ __align__(16) float g_bL[2][2048];         // bih+bhh, gate-interleaved
__device__ unsigned g_count = 0;
__device__ volatile unsigned g_gen = 0;

// ---------------- helpers ----------------
__device__ __forceinline__ unsigned f2tf(float x){
  unsigned u; asm("cvt.rna.tf32.f32 %0, %1;" : "=r"(u) : "f"(x)); return u;
}
__device__ __forceinline__ float tf32r(float x){ return __uint_as_float(f2tf(x)); }

__device__ __forceinline__ void cpa16(float* d, const float* s){
  unsigned u = (unsigned)__cvta_generic_to_shared(d);
  asm volatile("cp.async.cg.shared.global [%0], [%1], 16;" :: "r"(u), "l"(s));
}
__device__ __forceinline__ float sigm(float x){ return 1.f/(1.f + __expf(-x)); }

// grid-wide sense-reversing barrier (all 128 CTAs resident)
__device__ __forceinline__ void gbar(){
  __threadfence();
  __syncthreads();
  if (threadIdx.x == 0){
    unsigned g = g_gen;
    unsigned t = atomicAdd(&g_count, 1u);
    if (t == gridDim.x - 1){
      g_count = 0;
      __threadfence();
      g_gen = g + 1;
    } else {
      while (g_gen == g) { }
    }
    __threadfence();
  }
  __syncthreads();
}

// ---------------- tiled tf32 GEMM: BM = MI*32, BN = 64, KC = 64, double-buffered cp.async ----
// A rows: [A1 (k < 512) | A2 (k >= 512)] when A2 != null (both stride = astride).
// B is k-major [K][N] (pre-transposed, pre-rounded to tf32).
template<int MI>
__device__ void run_gemm(const float* A1, const float* A2, int astride,
                         const float* Bw, int bstride, int K,
                         int mt, int nt, float* sm, float (&acc)[2][2][4])
{
  float* Asb[2] = { sm, sm + 64*SMS };
  float* Bsb[2] = { sm + 2*64*SMS, sm + 3*64*SMS };
  const int tid  = threadIdx.x;
  const int wid  = tid >> 5, lane = tid & 31;
  const int wm   = wid >> 2, wn = wid & 3;
  const int gg   = lane >> 2, qq = lane & 3;
  const int BM   = MI * 32;

  #pragma unroll
  for (int mi = 0; mi < MI; mi++)
    #pragma unroll
    for (int ni = 0; ni < 2; ni++)
      #pragma unroll
      for (int r = 0; r < 4; r++) acc[mi][ni][r] = 0.f;

  const int nc = K / 64;

  auto load_chunk = [&](int c, int buf){
    int kc = c * 64;
    const float* Ab = (A2 != nullptr && kc >= 512)
        ? (A2 + (size_t)mt*BM*astride + (kc - 512))
        : (A1 + (size_t)mt*BM*astride + kc);
    const float* Bb = Bw + (size_t)kc*bstride + nt*64;
    #pragma unroll
    for (int i = 0; i < MI*2; i++){
      int id = tid + i*256; int r = id >> 4, c4 = (id & 15) * 4;
      cpa16(Asb[buf] + r*SMS + c4, Ab + (size_t)r*astride + c4);
    }
    #pragma unroll
    for (int i = 0; i < 4; i++){
      int id = tid + i*256; int r = id >> 4, c4 = (id & 15) * 4;
      cpa16(Bsb[buf] + r*SMS + c4, Bb + (size_t)r*bstride + c4);
    }
    asm volatile("cp.async.commit_group;");
  };

  load_chunk(0, 0);
  for (int c = 0; c < nc; c++){
    int buf = c & 1;
    if (c + 1 < nc){
      load_chunk(c + 1, buf ^ 1);
      asm volatile("cp.async.wait_group 1;");
    } else {
      asm volatile("cp.async.wait_group 0;");
    }
    __syncthreads();
    const float* Ac = Asb[buf];
    const float* Bc = Bsb[buf];
    #pragma unroll
    for (int kk = 0; kk < 64; kk += 8){
      unsigned af[MI][4], bf[2][2];
      #pragma unroll
      for (int mi = 0; mi < MI; mi++){
        const float* p = Ac + (wm*MI*16 + mi*16 + gg)*SMS + kk + qq;
        af[mi][0] = f2tf(p[0]);
        af[mi][1] = f2tf(p[8*SMS]);
        af[mi][2] = f2tf(p[4]);
        af[mi][3] = f2tf(p[8*SMS + 4]);
      }
      #pragma unroll
      for (int ni = 0; ni < 2; ni++){
        const float* p = Bc + (kk + qq)*SMS + wn*16 + ni*8 + gg;
        bf[ni][0] = __float_as_uint(p[0]);        // weights pre-rounded to tf32
        bf[ni][1] = __float_as_uint(p[4*SMS]);
      }
      #pragma unroll
      for (int mi = 0; mi < MI; mi++)
        #pragma unroll
        for (int ni = 0; ni < 2; ni++)
          asm volatile(
            "mma.sync.aligned.m16n8k8.row.col.f32.tf32.tf32.f32 "
            "{%0,%1,%2,%3},{%4,%5,%6,%7},{%8,%9},{%0,%1,%2,%3};"
            : "+f"(acc[mi][ni][0]), "+f"(acc[mi][ni][1]),
              "+f"(acc[mi][ni][2]), "+f"(acc[mi][ni][3])
            : "r"(af[mi][0]), "r"(af[mi][1]), "r"(af[mi][2]), "r"(af[mi][3]),
              "r"(bf[ni][0]), "r"(bf[ni][1]));
    }
    __syncthreads();
  }
}

// stage accumulators into Gs (aliases As buffer 0, safe after mainloop)
template<int MI>
__device__ void stage_acc(float* Gs, float (&acc)[2][2][4]){
  const int tid = threadIdx.x, wid = tid >> 5, lane = tid & 31;
  const int wm = wid >> 2, wn = wid & 3, gg = lane >> 2, qq = lane & 3;
  #pragma unroll
  for (int mi = 0; mi < MI; mi++)
    #pragma unroll
    for (int ni = 0; ni < 2; ni++){
      int r0 = wm*MI*16 + mi*16 + gg;
      int c0 = wn*16 + ni*8 + qq*2;
      Gs[r0*SMS + c0]       = acc[mi][ni][0];
      Gs[r0*SMS + c0 + 1]   = acc[mi][ni][1];
      Gs[(r0+8)*SMS + c0]     = acc[mi][ni][2];
      Gs[(r0+8)*SMS + c0 + 1] = acc[mi][ni][3];
    }
  __syncthreads();
}

// ---------------- the persistent decoder kernel ----------------
__global__ void __launch_bounds__(256, 1)
decoder_kernel(const float* __restrict__ latent, const float* __restrict__ fc_b,
               const float* __restrict__ map_b, float* __restrict__ outs)
{
  extern __shared__ float sm[];
  float* Gs = sm;               // alias of As buffer 0
  float acc[2][2][4];
  const int tile = blockIdx.x;
  const int tid  = threadIdx.x;

  // ---- init: dec = tanh(latent @ fc_w.T + fc_b); FC = dec; fill H[0], C[0]
  if (tile < 128){
    int mt = tile >> 5, nt = tile & 31;
    run_gemm<2>(latent, nullptr, 256, g_Bfc, 2048, 256, mt, nt, sm, acc);
    stage_acc<2>(Gs, acc);
    #pragma unroll
    for (int e = 0; e < 16; e++){
      int idx = tid + e*256;
      int rl = idx >> 6, cl = idx & 63;
      int r = mt*64 + rl, c = nt*64 + cl;
      float v = tanhf(Gs[rl*SMS + cl] + fc_b[c]);
      __stcg(&g_FC[r*2048 + c], v);
      int l = r >> 7;
      int b = ((r & 127) << 1) | (c >> 10);
      int j = c & 1023;
      if (j < 512) __stcg(&g_H[0][l][b*512 + j], v);
      else         __stcg(&g_C[0][l][b*512 + j - 512], v);
    }
  }
  gbar();

  for (int t = 0; t < NSTEP; t++){
    int par = t & 1;
    // ---- phase 1: OUT = sigmoid(FC @ map_w.T + map_b); write outs[t]
    if (tile < 64){
      int mt = tile >> 3, nt = tile & 7;
      run_gemm<1>(g_FC, nullptr, 2048, g_Bmap, 512, 2048, mt, nt, sm, acc);
      stage_acc<1>(Gs, acc);
      #pragma unroll
      for (int e = 0; e < 8; e++){
        int idx = tid + e*256;
        int rl = idx >> 6, cl = idx & 63;
        int gr = mt*32 + rl, gc = nt*64 + cl;
        float v = sigm(Gs[rl*SMS + cl] + map_b[gc]);
        __stcg(&g_OUT[gr*512 + gc], v);
        __stcs(&outs[(size_t)t*131072 + gr*512 + gc], v);
      }
    }
    gbar();
    // ---- phases 2,3: LSTM layers with fused cell epilogue
    #pragma unroll 1
    for (int l = 0; l < 2; l++){
      if (tile < 128){
        int mt = tile >> 5, nt = tile & 31;
        const float* X = (l == 0) ? g_OUT : g_X1;
        run_gemm<2>(X, g_H[par][l], 512, g_BL[l], 2048, 1024, mt, nt, sm, acc);
        stage_acc<2>(Gs, acc);
        #pragma unroll
        for (int e = 0; e < 4; e++){
          int pid = tid + e*256;
          int bl = pid >> 4, ul = pid & 15;
          float4 gq = *(const float4*)&Gs[bl*SMS + ul*4];       // (i,f,g,o) interleaved
          float4 bq = *(const float4*)&g_bL[l][nt*64 + ul*4];
          int b = mt*64 + bl;
          int U = nt*16 + ul;
          float cp = __ldcg(&g_C[par][l][b*512 + U]);
          float ig = sigm(gq.x + bq.x);
          float fg = sigm(gq.y + bq.y);
          float gt = tanhf(gq.z + bq.z);
          float og = sigm(gq.w + bq.w);
          float c2 = fg*cp + ig*gt;
          float h2 = og*tanhf(c2);
          float th = tanhf(h2);
          float tc = tanhf(c2);
          __stcg(&g_H[par^1][l][b*512 + U], th);
          __stcg(&g_C[par^1][l][b*512 + U], tc);
          if (l == 0) __stcg(&g_X1[b*512 + U], h2);
          int row = l*128 + (b >> 1);
          int col = ((b & 1) << 10) | U;
          __stcg(&g_FC[row*2048 + col], th);
          __stcg(&g_FC[row*2048 + col + 512], tc);
        }
      }
      gbar();
    }
  }
}

// ---------------- weight prep (transpose + tf32 round + gate interleave) ----------------
__global__ void prep_fc_k(const float* __restrict__ fc_w){
  int i = blockIdx.x*256 + threadIdx.x;
  if (i < 256*2048){ int k = i >> 11, n = i & 2047; g_Bfc[i] = tf32r(fc_w[n*256 + k]); }
}
__global__ void prep_map_k(const float* __restrict__ map_w){
  int i = blockIdx.x*256 + threadIdx.x;
  if (i < 2048*512){ int k = i >> 9, n = i & 511; g_Bmap[i] = tf32r(map_w[n*2048 + k]); }
}
__global__ void prep_gate_k(const float* __restrict__ wih, const float* __restrict__ whh, int l){
  int i = blockIdx.x*256 + threadIdx.x;
  if (i < 1024*2048){
    int k = i >> 11, n = i & 2047;
    int u = n >> 2, g = n & 3, orow = g*512 + u;
    float v = (k < 512) ? wih[orow*512 + k] : whh[orow*512 + (k - 512)];
    g_BL[l][i] = tf32r(v);
  }
}
__global__ void prep_bias_k(const float* __restrict__ bih, const float* __restrict__ bhh, int l){
  int n = blockIdx.x*256 + threadIdx.x;
  if (n < 2048){ int u = n >> 2, g = n & 3, orow = g*512 + u; g_bL[l][n] = bih[orow] + bhh[orow]; }
}

// ---------------- launch ----------------
extern "C" void kernel_launch(void* const* d_in, const int* in_sizes, int n_in,
                              void* d_out, int out_size)
{
  const float* latent = (const float*)d_in[0];
  const float* fc_w   = (const float*)d_in[1];
  const float* fc_b   = (const float*)d_in[2];
  const float* map_w  = (const float*)d_in[3];
  const float* map_b  = (const float*)d_in[4];
  const float* wih0   = (const float*)d_in[5];
  const float* whh0   = (const float*)d_in[6];
  const float* bih0   = (const float*)d_in[7];
  const float* bhh0   = (const float*)d_in[8];
  const float* wih1   = (const float*)d_in[9];
  const float* whh1   = (const float*)d_in[10];
  const float* bih1   = (const float*)d_in[11];
  const float* bhh1   = (const float*)d_in[12];

  const int smem = 4*64*SMS*4;  // 69632 bytes
  cudaFuncSetAttribute(decoder_kernel, cudaFuncAttributeMaxDynamicSharedMemorySize, smem);

  prep_fc_k  <<<2048, 256>>>(fc_w);
  prep_map_k <<<4096, 256>>>(map_w);
  prep_gate_k<<<8192, 256>>>(wih0, whh0, 0);
  prep_gate_k<<<8192, 256>>>(wih1, whh1, 1);
  prep_bias_k<<<8,    256>>>(bih0, bhh0, 0);
  prep_bias_k<<<8,    256>>>(bih1, bhh1, 1);

  decoder_kernel<<<128, 256, smem>>>(latent, fc_b, map_b, (float*)d_out);
}

// round 5
// speedup vs baseline: 1.2333x; 1.2333x over previous
#include <cuda_runtime.h>
#include <cstdint>

#define SMS 68          // smem row stride in floats (bank-conflict-free, 16B-aligned)
#define NSTEP 256

// ---------------- persistent device state (no allocation allowed) ----------------
__device__ __align__(16) float g_FC[256*2048];        // fc_in-layout state (tf32-rounded)
__device__ __align__(16) float g_OUT[256*512];        // tf32(sigmoid(map)) (x for layer0)
__device__ __align__(16) float g_X1[256*512];         // tf32 raw h2 of layer0 (x for layer1)
__device__ __align__(16) float g_H[2][2][256*512];    // [parity][layer] tf32 tanh(h)
__device__ __align__(16) float g_C[2][2][256*512];    // [parity][layer] tf32 tanh(c)
__device__ __align__(16) float g_LAT[256*256];        // tf32-rounded latent
__device__ __align__(16) float g_Bfc[256*2048];       // tf32 fc_w, k-major
__device__ __align__(16) float g_Bmap[2048*512];      // tf32 map_w, k-major
__device__ __align__(16) float g_BL[2][1024*2048];    // tf32 [wih;whh], gate-interleaved cols
__device__ __align__(16) float g_bL[2][2048];         // bih+bhh, gate-interleaved
__device__ unsigned g_count = 0;
__device__ volatile unsigned g_gen = 0;

// ---------------- helpers ----------------
__device__ __forceinline__ unsigned f2tf(float x){
  unsigned u; asm("cvt.rna.tf32.f32 %0, %1;" : "=r"(u) : "f"(x)); return u;
}
__device__ __forceinline__ float tf32r(float x){ return __uint_as_float(f2tf(x)); }

__device__ __forceinline__ void cpa16(float* d, const float* s){
  unsigned u = (unsigned)__cvta_generic_to_shared(d);
  asm volatile("cp.async.cg.shared.global [%0], [%1], 16;" :: "r"(u), "l"(s));
}
__device__ __forceinline__ float sigm(float x){ return 1.f/(1.f + __expf(-x)); }

// grid-wide sense-reversing barrier (128 CTAs, all resident: 1 CTA/SM)
__device__ __forceinline__ void gbar(){
  __threadfence();
  __syncthreads();
  if (threadIdx.x == 0){
    unsigned g = g_gen;
    unsigned t = atomicAdd(&g_count, 1u);
    if (t == gridDim.x - 1){
      g_count = 0;
      __threadfence();
      g_gen = g + 1;
    } else {
      while (g_gen == g) { }
    }
    __threadfence();
  }
  __syncthreads();
}

// ---------------- tiled tf32 GEMM: BM = MI*32, BN = 64, KC = 64, 4-stage cp.async ring ----
// A rows: [A1 (k < 512) | A2 (k >= 512)] when A2 != null (both stride = astride).
// B is k-major [K][N] (pre-transposed, tf32-rounded). A is tf32-rounded at its producer.
template<int MI>
__device__ void run_gemm(const float* A1, const float* A2, int astride,
                         const float* Bw, int bstride, int K,
                         int mt, int nt, float* sm, float (&acc)[2][2][4])
{
  const int tid  = threadIdx.x;
  const int wid  = tid >> 5, lane = tid & 31;
  const int wm   = wid >> 2, wn = wid & 3;
  const int gg   = lane >> 2, qq = lane & 3;
  const int BM   = MI * 32;

  #pragma unroll
  for (int mi = 0; mi < MI; mi++)
    #pragma unroll
    for (int ni = 0; ni < 2; ni++)
      #pragma unroll
      for (int r = 0; r < 4; r++) acc[mi][ni][r] = 0.f;

  const int nc = K / 64;      // >= 4 in all phases

  auto load_chunk = [&](int c, int s){
    float* As = sm + s * (128*SMS);
    float* Bs = As + 64*SMS;
    int kc = c * 64;
    const float* Ab = (A2 != nullptr && kc >= 512)
        ? (A2 + (size_t)mt*BM*astride + (kc - 512))
        : (A1 + (size_t)mt*BM*astride + kc);
    const float* Bb = Bw + (size_t)kc*bstride + nt*64;
    #pragma unroll
    for (int i = 0; i < MI*2; i++){
      int id = tid + i*256; int r = id >> 4, c4 = (id & 15) * 4;
      cpa16(As + r*SMS + c4, Ab + (size_t)r*astride + c4);
    }
    #pragma unroll
    for (int i = 0; i < 4; i++){
      int id = tid + i*256; int r = id >> 4, c4 = (id & 15) * 4;
      cpa16(Bs + r*SMS + c4, Bb + (size_t)r*bstride + c4);
    }
    asm volatile("cp.async.commit_group;");
  };

  load_chunk(0, 0);
  load_chunk(1, 1);
  load_chunk(2, 2);

  for (int c = 0; c < nc; c++){
    int buf = c & 3;
    if (c + 3 < nc){
      load_chunk(c + 3, (c + 3) & 3);
      asm volatile("cp.async.wait_group 3;");
    } else {
      int p = nc - 1 - c;
      if (p == 2)      asm volatile("cp.async.wait_group 2;");
      else if (p == 1) asm volatile("cp.async.wait_group 1;");
      else             asm volatile("cp.async.wait_group 0;");
    }
    __syncthreads();
    const float* Ac = sm + buf * (128*SMS);
    const float* Bc = Ac + 64*SMS;
    #pragma unroll
    for (int kk = 0; kk < 64; kk += 8){
      unsigned af[MI][4], bf[2][2];
      #pragma unroll
      for (int mi = 0; mi < MI; mi++){
        const float* p = Ac + (wm*MI*16 + mi*16 + gg)*SMS + kk + qq;
        af[mi][0] = __float_as_uint(p[0]);
        af[mi][1] = __float_as_uint(p[8*SMS]);
        af[mi][2] = __float_as_uint(p[4]);
        af[mi][3] = __float_as_uint(p[8*SMS + 4]);
      }
      #pragma unroll
      for (int ni = 0; ni < 2; ni++){
        const float* p = Bc + (kk + qq)*SMS + wn*16 + ni*8 + gg;
        bf[ni][0] = __float_as_uint(p[0]);
        bf[ni][1] = __float_as_uint(p[4*SMS]);
      }
      #pragma unroll
      for (int mi = 0; mi < MI; mi++)
        #pragma unroll
        for (int ni = 0; ni < 2; ni++)
          asm volatile(
            "mma.sync.aligned.m16n8k8.row.col.f32.tf32.tf32.f32 "
            "{%0,%1,%2,%3},{%4,%5,%6,%7},{%8,%9},{%0,%1,%2,%3};"
            : "+f"(acc[mi][ni][0]), "+f"(acc[mi][ni][1]),
              "+f"(acc[mi][ni][2]), "+f"(acc[mi][ni][3])
            : "r"(af[mi][0]), "r"(af[mi][1]), "r"(af[mi][2]), "r"(af[mi][3]),
              "r"(bf[ni][0]), "r"(bf[ni][1]));
    }
    __syncthreads();
  }
}

// stage accumulators into Gs (aliases stage-0 A buffer, safe after mainloop)
template<int MI>
__device__ void stage_acc(float* Gs, float (&acc)[2][2][4]){
  const int tid = threadIdx.x, wid = tid >> 5, lane = tid & 31;
  const int wm = wid >> 2, wn = wid & 3, gg = lane >> 2, qq = lane & 3;
  #pragma unroll
  for (int mi = 0; mi < MI; mi++)
    #pragma unroll
    for (int ni = 0; ni < 2; ni++){
      int r0 = wm*MI*16 + mi*16 + gg;
      int c0 = wn*16 + ni*8 + qq*2;
      Gs[r0*SMS + c0]       = acc[mi][ni][0];
      Gs[r0*SMS + c0 + 1]   = acc[mi][ni][1];
      Gs[(r0+8)*SMS + c0]     = acc[mi][ni][2];
      Gs[(r0+8)*SMS + c0 + 1] = acc[mi][ni][3];
    }
  __syncthreads();
}

// ---------------- the persistent decoder kernel ----------------
__global__ void __launch_bounds__(256, 1)
decoder_kernel(const float* __restrict__ fc_b,
               const float* __restrict__ map_b, float* __restrict__ outs)
{
  extern __shared__ float sm[];
  float* Gs = sm;               // alias of stage-0 A buffer
  float acc[2][2][4];
  const int tile = blockIdx.x;
  const int tid  = threadIdx.x;

  // ---- init: dec = tanh(latent @ fc_w.T + fc_b); FC = dec; fill H[0], C[0]
  if (tile < 128){
    int mt = tile >> 5, nt = tile & 31;
    run_gemm<2>(g_LAT, nullptr, 256, g_Bfc, 2048, 256, mt, nt, sm, acc);
    stage_acc<2>(Gs, acc);
    #pragma unroll
    for (int e = 0; e < 16; e++){
      int idx = tid + e*256;
      int rl = idx >> 6, cl = idx & 63;
      int r = mt*64 + rl, c = nt*64 + cl;
      float v = tf32r(tanhf(Gs[rl*SMS + cl] + fc_b[c]));
      __stcg(&g_FC[r*2048 + c], v);
      int l = r >> 7;
      int b = ((r & 127) << 1) | (c >> 10);
      int j = c & 1023;
      if (j < 512) __stcg(&g_H[0][l][b*512 + j], v);
      else         __stcg(&g_C[0][l][b*512 + j - 512], v);
    }
  }
  gbar();

  for (int t = 0; t < NSTEP; t++){
    int par = t & 1;
    // ---- phase 1: OUT = sigmoid(FC @ map_w.T + map_b); write outs[t]
    if (tile < 64){
      int mt = tile >> 3, nt = tile & 7;
      run_gemm<1>(g_FC, nullptr, 2048, g_Bmap, 512, 2048, mt, nt, sm, acc);
      stage_acc<1>(Gs, acc);
      #pragma unroll
      for (int e = 0; e < 8; e++){
        int idx = tid + e*256;
        int rl = idx >> 6, cl = idx & 63;
        int gr = mt*32 + rl, gc = nt*64 + cl;
        float v = sigm(Gs[rl*SMS + cl] + map_b[gc]);
        __stcg(&g_OUT[gr*512 + gc], tf32r(v));
        __stcs(&outs[(size_t)t*131072 + gr*512 + gc], v);
      }
    }
    gbar();
    // ---- phases 2,3: LSTM layers with fused cell epilogue
    #pragma unroll 1
    for (int l = 0; l < 2; l++){
      if (tile < 128){
        int mt = tile >> 5, nt = tile & 31;
        const float* X = (l == 0) ? g_OUT : g_X1;
        run_gemm<2>(X, g_H[par][l], 512, g_BL[l], 2048, 1024, mt, nt, sm, acc);
        stage_acc<2>(Gs, acc);
        #pragma unroll
        for (int e = 0; e < 4; e++){
          int pid = tid + e*256;
          int bl = pid >> 4, ul = pid & 15;
          float4 gq = *(const float4*)&Gs[bl*SMS + ul*4];       // (i,f,g,o) interleaved
          float4 bq = *(const float4*)&g_bL[l][nt*64 + ul*4];
          int b = mt*64 + bl;
          int U = nt*16 + ul;
          float cp = __ldcg(&g_C[par][l][b*512 + U]);
          float ig = sigm(gq.x + bq.x);
          float fg = sigm(gq.y + bq.y);
          float gt = tanhf(gq.z + bq.z);
          float og = sigm(gq.w + bq.w);
          float c2 = fg*cp + ig*gt;
          float h2 = og*tanhf(c2);
          float th = tf32r(tanhf(h2));
          float tc = tf32r(tanhf(c2));
          __stcg(&g_H[par^1][l][b*512 + U], th);
          __stcg(&g_C[par^1][l][b*512 + U], tc);
          if (l == 0) __stcg(&g_X1[b*512 + U], tf32r(h2));
          int row = l*128 + (b >> 1);
          int col = ((b & 1) << 10) | U;
          __stcg(&g_FC[row*2048 + col], th);
          __stcg(&g_FC[row*2048 + col + 512], tc);
        }
      }
      gbar();
    }
  }
}

// ---------------- single merged weight-prep kernel ----------------
// segment layout: Bfc 524288 | Bmap 1048576 | BL0 2097152 | BL1 2097152 |
//                 bias0 2048 | bias1 2048 | latent 65536   (total 5836800)
__global__ void prep_all(const float* __restrict__ latent,
                         const float* __restrict__ fc_w,
                         const float* __restrict__ map_w,
                         const float* __restrict__ wih0, const float* __restrict__ whh0,
                         const float* __restrict__ wih1, const float* __restrict__ whh1,
                         const float* __restrict__ bih0, const float* __restrict__ bhh0,
                         const float* __restrict__ bih1, const float* __restrict__ bhh1)
{
  int i = blockIdx.x*256 + threadIdx.x;
  if (i < 524288){
    int k = i >> 11, n = i & 2047;
    g_Bfc[i] = tf32r(fc_w[n*256 + k]);
    return;
  }
  i -= 524288;
  if (i < 1048576){
    int k = i >> 9, n = i & 511;
    g_Bmap[i] = tf32r(map_w[n*2048 + k]);
    return;
  }
  i -= 1048576;
  if (i < 4194304){
    int l = i >> 21; int j = i & 2097151;
    int k = j >> 11, n = j & 2047;
    int u = n >> 2, g = n & 3, orow = g*512 + u;
    const float* wih = l ? wih1 : wih0;
    const float* whh = l ? whh1 : whh0;
    float v = (k < 512) ? wih[orow*512 + k] : whh[orow*512 + (k - 512)];
    g_BL[l][j] = tf32r(v);
    return;
  }
  i -= 4194304;
  if (i < 4096){
    int l = i >> 11; int n = i & 2047;
    int u = n >> 2, g = n & 3, orow = g*512 + u;
    const float* bih = l ? bih1 : bih0;
    const float* bhh = l ? bhh1 : bhh0;
    g_bL[l][n] = bih[orow] + bhh[orow];
    return;
  }
  i -= 4096;
  if (i < 65536){
    g_LAT[i] = tf32r(latent[i]);
  }
}

// ---------------- launch ----------------
extern "C" void kernel_launch(void* const* d_in, const int* in_sizes, int n_in,
                              void* d_out, int out_size)
{
  const float* latent = (const float*)d_in[0];
  const float* fc_w   = (const float*)d_in[1];
  const float* fc_b   = (const float*)d_in[2];
  const float* map_w  = (const float*)d_in[3];
  const float* map_b  = (const float*)d_in[4];
  const float* wih0   = (const float*)d_in[5];
  const float* whh0   = (const float*)d_in[6];
  const float* bih0   = (const float*)d_in[7];
  const float* bhh0   = (const float*)d_in[8];
  const float* wih1   = (const float*)d_in[9];
  const float* whh1   = (const float*)d_in[10];
  const float* bih1   = (const float*)d_in[11];
  const float* bhh1   = (const float*)d_in[12];

  const int smem = 4*128*SMS*4;  // 139264 bytes (4-stage ring, A+B per stage)
  cudaFuncSetAttribute(decoder_kernel, cudaFuncAttributeMaxDynamicSharedMemorySize, smem);

  prep_all<<<22800, 256>>>(latent, fc_w, map_w, wih0, whh0, wih1, whh1,
                           bih0, bhh0, bih1, bhh1);
  decoder_kernel<<<128, 256, smem>>>(fc_b, map_b, (float*)d_out);
}